// round 12
// baseline (speedup 1.0000x reference)
#include <cuda_runtime.h>
#include <cuda_fp16.h>
#include <math.h>
#include <stdint.h>

#define T_TOK 32768
#define DIM   128
#define KC    8192
#define BM    128
#define ITERS2 64                 /* 128 codes per iteration */
#define GRID_GEMM (T_TOK / BM)    /* 256 */
#define TILE_BYTES 16384          /* per 64-code subtile */
#define SLOT_BYTES 32768          /* 128-code slot */
#define SMEM_GEMM (3 * SLOT_BYTES)  /* 96KB ring */
#define PAD 132
#define SMEM_PROJ (2 * 128 * PAD * 4)

/* ---------------- device scratch (no allocations) ---------------- */
__device__ __align__(16) unsigned char g_cbt[128 * TILE_BYTES]; /* 2MB fp16 B frags */
__device__ float  g_codebook[KC * DIM];
__device__ __align__(16) float g_cnorm[KC];
__device__ int    g_counts[KC];
__device__ double g_ssep[GRID_GEMM];
__device__ unsigned int g_done;

__device__ __forceinline__ uint32_t smem_u32(const void* p) {
    uint32_t a;
    asm("{ .reg .u64 t; cvta.to.shared.u64 t, %1; cvt.u32.u64 %0, t; }"
        : "=r"(a) : "l"(p));
    return a;
}

#define CP16(dst, src) \
    asm volatile("cp.async.cg.shared.global [%0], [%1], 16;" :: "r"((uint32_t)(dst)), "l"(src))
#define CP_COMMIT() asm volatile("cp.async.commit_group;" ::: "memory")
#define CP_WAIT1()  asm volatile("cp.async.wait_group 1;"  ::: "memory")
#define CP_WAIT0()  asm volatile("cp.async.wait_group 0;"  ::: "memory")

#define MMA_F16(d, a, b0, b1) \
    asm volatile("mma.sync.aligned.m16n8k16.row.col.f32.f16.f16.f32 " \
                 "{%0,%1,%2,%3}, {%4,%5,%6,%7}, {%8,%9}, {%0,%1,%2,%3};" \
                 : "+f"((d)[0]), "+f"((d)[1]), "+f"((d)[2]), "+f"((d)[3]) \
                 : "r"((a)[0]), "r"((a)[1]), "r"((a)[2]), "r"((a)[3]), \
                   "r"(b0), "r"(b1))

#define INS4(tv0, tv1, tv2, tv3, ti0, ti1, ti2, ti3, v, n) do {               \
    if ((v) < (tv3)) {                                                        \
        if ((v) < (tv2)) {                                                    \
            tv3 = tv2; ti3 = ti2;                                             \
            if ((v) < (tv1)) {                                                \
                tv2 = tv1; ti2 = ti1;                                         \
                if ((v) < (tv0)) { tv1 = tv0; ti1 = ti0; tv0 = (v); ti0 = (n); } \
                else             { tv1 = (v); ti1 = (n); }                    \
            } else { tv2 = (v); ti2 = (n); }                                  \
        } else { tv3 = (v); ti3 = (n); }                                      \
    }                                                                         \
} while (0)

/* ---------------- projection GEMM: C = emb @ W^T + b (128 codes/block) ----------------
   Emits fp32 codebook, cnorm, fp16 packed B fragments; zeroes g_counts and g_done.
   Packed layout per 64-code tile (16KB): [nblk(8)][kpair(4)][lane(32)] x 16B,
   16B = {frag(kblk=2p) 8B, frag(kblk=2p+1) 8B}; within 8B: regsel(2) x par(2) fp16;
   lane = nl*4 + ksub; n = tile*64 + nblk*8 + nl, k = kblk*16 + regsel*8 + ksub*2 + par */
__global__ __launch_bounds__(256, 1)
void k_proj(const float* __restrict__ emb,
            const float* __restrict__ pw,
            const float* __restrict__ pbias) {
    extern __shared__ float ps[];
    float* es = ps;
    float* wsm = ps + 128 * PAD;
    const int tid = threadIdx.x;
    const int tx = tid & 15, ty = tid >> 4;
    const int c0 = blockIdx.x * 128;

    if (tid < 128) g_counts[c0 + tid] = 0;
    if (blockIdx.x == 0 && tid == 0) g_done = 0;

#pragma unroll
    for (int i = 0; i < 16; i++) {
        int f = tid + i * 256;
        int row = f >> 5;
        int c4 = f & 31;
        int sw = (((row >> 2) ^ (c4 & 7)) << 2) | (row & 3);
        float4 v = *((const float4*)(emb + (size_t)(c0 + row) * DIM) + c4);
        es[(4 * c4 + 0) * PAD + sw] = v.x;
        es[(4 * c4 + 1) * PAD + sw] = v.y;
        es[(4 * c4 + 2) * PAD + sw] = v.z;
        es[(4 * c4 + 3) * PAD + sw] = v.w;
        float4 w = *((const float4*)(pw + (size_t)row * DIM) + c4);
        wsm[(4 * c4 + 0) * PAD + sw] = w.x;
        wsm[(4 * c4 + 1) * PAD + sw] = w.y;
        wsm[(4 * c4 + 2) * PAD + sw] = w.z;
        wsm[(4 * c4 + 3) * PAD + sw] = w.w;
    }
    __syncthreads();

    float acc[8][8];
#pragma unroll
    for (int im = 0; im < 8; im++)
#pragma unroll
        for (int jn = 0; jn < 8; jn++) acc[im][jn] = 0.0f;

#pragma unroll 4
    for (int k = 0; k < 128; k++) {
        int s = (k >> 2) & 7;
        const float* er = es + k * PAD;
        const float* wr = wsm + k * PAD;
        float4 a0 = *(const float4*)(er + ((ty ^ s) << 2));
        float4 a1 = *(const float4*)(er + 64 + ((ty ^ s) << 2));
        float4 b0 = *(const float4*)(wr + ((tx ^ s) << 2));
        float4 b1 = *(const float4*)(wr + 64 + ((tx ^ s) << 2));
        float a[8] = {a0.x, a0.y, a0.z, a0.w, a1.x, a1.y, a1.z, a1.w};
        float b[8] = {b0.x, b0.y, b0.z, b0.w, b1.x, b1.y, b1.z, b1.w};
#pragma unroll
        for (int im = 0; im < 8; im++)
#pragma unroll
            for (int jn = 0; jn < 8; jn++)
                acc[im][jn] = fmaf(a[im], b[jn], acc[im][jn]);
    }

    float cnp[8];
#pragma unroll
    for (int im = 0; im < 8; im++) cnp[im] = 0.0f;

#pragma unroll
    for (int im = 0; im < 8; im++) {
        int cl = (im < 4) ? (ty * 4 + im) : (64 + ty * 4 + im - 4);
        int cg = c0 + cl;
        int tile = cg >> 6, nblk = (cg >> 3) & 7, nl = cg & 7;
#pragma unroll
        for (int jn = 0; jn < 8; jn++) {
            int d = (jn < 4) ? (tx * 4 + jn) : (64 + tx * 4 + jn - 4);
            float val = acc[im][jn] + pbias[d];
            g_codebook[(size_t)cg * DIM + d] = val;
            cnp[im] = fmaf(val, val, cnp[im]);
            int kblk = d >> 4, kin = d & 15;
            int regsel = kin >> 3, ksub = (kin & 7) >> 1, par = kin & 1;
            int kpair = kblk >> 1, khalf = kblk & 1;
            int lane = nl * 4 + ksub;
            size_t off = (size_t)tile * TILE_BYTES + nblk * 2048 + kpair * 512
                       + lane * 16 + khalf * 8 + regsel * 4 + par * 2;
            *(__half*)(g_cbt + off) = __float2half_rn(val);
        }
    }
#pragma unroll
    for (int im = 0; im < 8; im++) {
#pragma unroll
        for (int o = 8; o > 0; o >>= 1)
            cnp[im] += __shfl_xor_sync(0xffffffffu, cnp[im], o, 16);
    }
    if (tx == 0) {
#pragma unroll
        for (int im = 0; im < 8; im++) {
            int cl = (im < 4) ? (ty * 4 + im) : (64 + ty * 4 + im - 4);
            g_cnorm[c0 + cl] = cnp[im];
        }
    }
}

/* ---------------- fused: fp16 HMMA GEMM + top-4 + exact rescore + loss/perplexity ----------------
   128 codes per loop iteration (two 64-code subtiles), v4 B loads (1 LDS -> 2 MMA). */
__global__ __launch_bounds__(256, 2)
void k_gemm(const float* __restrict__ z, float* __restrict__ out) {
    extern __shared__ unsigned char smem[];
    const uint32_t sb = smem_u32(smem);
    const int tid = threadIdx.x;
    const int lane = tid & 31;
    const int warp = tid >> 5;
    const int r = lane >> 2;
    const int cc = lane & 3;
    const int m0 = blockIdx.x * BM;

    /* prologue: prefetch 128-code slots 0 and 1 (32KB each: 8 CP16/thread) */
#pragma unroll
    for (int t = 0; t < 2; t++) {
        const unsigned char* src = g_cbt + (size_t)t * SLOT_BYTES;
        uint32_t dst = sb + t * SLOT_BYTES;
#pragma unroll
        for (int j = 0; j < 8; j++) {
            uint32_t off = (uint32_t)(tid + j * 256) * 16;
            CP16(dst + off, src + off);
        }
        CP_COMMIT();
    }

    /* A fragments (fp16) in registers */
    uint32_t A[8][4];
    {
        const float* z0 = z + (size_t)(m0 + warp * 16 + r) * DIM;
#pragma unroll
        for (int kb = 0; kb < 8; kb++) {
#pragma unroll
            for (int q = 0; q < 4; q++) {
                const float* src = z0 + ((q & 1) ? 8 * DIM : 0) + kb * 16 + (q >> 1) * 8 + cc * 2;
                float2 v = *(const float2*)src;
                __half2 hh = __floats2half2_rn(v.x, v.y);
                A[kb][q] = *(uint32_t*)&hh;
            }
        }
    }

    float av0 = 3.4e38f, av1 = 3.4e38f, av2 = 3.4e38f, av3 = 3.4e38f;
    float bv0 = 3.4e38f, bv1 = 3.4e38f, bv2 = 3.4e38f, bv3 = 3.4e38f;
    int ai0 = 0, ai1 = 0, ai2 = 0, ai3 = 0;
    int bi0 = 0, bi1 = 0, bi2 = 0, bi3 = 0;

    int buf = 0, nbuf = 2;
    for (int i = 0; i < ITERS2; i++) {
        CP_WAIT1();
        __syncthreads();
        if (i + 2 < ITERS2) {
            const unsigned char* src = g_cbt + (size_t)(i + 2) * SLOT_BYTES;
            uint32_t dst = sb + nbuf * SLOT_BYTES;
#pragma unroll
            for (int j = 0; j < 8; j++) {
                uint32_t off = (uint32_t)(tid + j * 256) * 16;
                CP16(dst + off, src + off);
            }
        }
        CP_COMMIT();

#pragma unroll
        for (int h = 0; h < 2; h++) {
            float acc[8][4];
#pragma unroll
            for (int nb = 0; nb < 8; nb++)
#pragma unroll
                for (int q = 0; q < 4; q++) acc[nb][q] = 0.0f;

            const uint32_t bbase = sb + buf * SLOT_BYTES + h * TILE_BYTES + lane * 16;
#pragma unroll
            for (int kp = 0; kp < 4; kp++) {
#pragma unroll
                for (int nb = 0; nb < 8; nb++) {
                    uint32_t b0, b1, b2, b3;
                    asm volatile("ld.shared.v4.b32 {%0,%1,%2,%3},[%4];"
                                 : "=r"(b0), "=r"(b1), "=r"(b2), "=r"(b3)
                                 : "r"(bbase + nb * 2048 + kp * 512));
                    MMA_F16(acc[nb], A[2 * kp], b0, b1);
                    MMA_F16(acc[nb], A[2 * kp + 1], b2, b3);
                }
            }

            const int n0i = i * 128 + h * 64;
#pragma unroll
            for (int nb = 0; nb < 8; nb++) {
                int n = n0i + nb * 8 + cc * 2;
                float2 cn = *(const float2*)(g_cnorm + n);
                float s0 = fmaf(-2.0f, acc[nb][0], cn.x);
                float s1 = fmaf(-2.0f, acc[nb][1], cn.y);
                float s2 = fmaf(-2.0f, acc[nb][2], cn.x);
                float s3 = fmaf(-2.0f, acc[nb][3], cn.y);
                INS4(av0, av1, av2, av3, ai0, ai1, ai2, ai3, s0, n);
                INS4(av0, av1, av2, av3, ai0, ai1, ai2, ai3, s1, n + 1);
                INS4(bv0, bv1, bv2, bv3, bi0, bi1, bi2, bi3, s2, n);
                INS4(bv0, bv1, bv2, bv3, bi0, bi1, bi2, bi3, s3, n + 1);
            }
        }
        buf = (buf == 2) ? 0 : buf + 1;
        nbuf = (nbuf == 2) ? 0 : nbuf + 1;
    }

    /* merge top-4 across the 4 cc lanes */
#pragma unroll
    for (int off = 1; off <= 2; off <<= 1) {
        float wa0 = __shfl_xor_sync(0xffffffffu, av0, off);
        float wa1 = __shfl_xor_sync(0xffffffffu, av1, off);
        float wa2 = __shfl_xor_sync(0xffffffffu, av2, off);
        float wa3 = __shfl_xor_sync(0xffffffffu, av3, off);
        int ja0 = __shfl_xor_sync(0xffffffffu, ai0, off);
        int ja1 = __shfl_xor_sync(0xffffffffu, ai1, off);
        int ja2 = __shfl_xor_sync(0xffffffffu, ai2, off);
        int ja3 = __shfl_xor_sync(0xffffffffu, ai3, off);
        float wb0 = __shfl_xor_sync(0xffffffffu, bv0, off);
        float wb1 = __shfl_xor_sync(0xffffffffu, bv1, off);
        float wb2 = __shfl_xor_sync(0xffffffffu, bv2, off);
        float wb3 = __shfl_xor_sync(0xffffffffu, bv3, off);
        int jb0 = __shfl_xor_sync(0xffffffffu, bi0, off);
        int jb1 = __shfl_xor_sync(0xffffffffu, bi1, off);
        int jb2 = __shfl_xor_sync(0xffffffffu, bi2, off);
        int jb3 = __shfl_xor_sync(0xffffffffu, bi3, off);
        INS4(av0, av1, av2, av3, ai0, ai1, ai2, ai3, wa0, ja0);
        INS4(av0, av1, av2, av3, ai0, ai1, ai2, ai3, wa1, ja1);
        INS4(av0, av1, av2, av3, ai0, ai1, ai2, ai3, wa2, ja2);
        INS4(av0, av1, av2, av3, ai0, ai1, ai2, ai3, wa3, ja3);
        INS4(bv0, bv1, bv2, bv3, bi0, bi1, bi2, bi3, wb0, jb0);
        INS4(bv0, bv1, bv2, bv3, bi0, bi1, bi2, bi3, wb1, jb1);
        INS4(bv0, bv1, bv2, bv3, bi0, bi1, bi2, bi3, wb2, jb2);
        INS4(bv0, bv1, bv2, bv3, bi0, bi1, bi2, bi3, wb3, jb3);
    }

    /* ---- fused rescore: stash candidates in smem (ring is drained) ---- */
    CP_WAIT0();
    __syncthreads();
    int4*  scand = (int4*)smem;                 /* 128 x 16B = 2KB */
    float* swsq  = (float*)(smem + 2048);
    int*   sflag = (int*)(smem + 2048 + 32);
    if (cc == 0) {
        scand[warp * 16 + r]     = make_int4(ai0, ai1, ai2, ai3);
        scand[warp * 16 + r + 8] = make_int4(bi0, bi1, bi2, bi3);
    }
    __syncthreads();

    float warp_sq = 0.0f;
    for (int j = 0; j < 16; j++) {
        const int tl = warp * 16 + j;
        const int t = m0 + tl;
        int4 cd = scand[tl];
        float4 zv = ((const float4*)(z + (size_t)t * DIM))[lane];
        float4 c0 = ((const float4*)(g_codebook + (size_t)cd.x * DIM))[lane];
        float4 c1 = ((const float4*)(g_codebook + (size_t)cd.y * DIM))[lane];
        float4 c2 = ((const float4*)(g_codebook + (size_t)cd.z * DIM))[lane];
        float4 c3 = ((const float4*)(g_codebook + (size_t)cd.w * DIM))[lane];
        float d0 = zv.x * c0.x + zv.y * c0.y + zv.z * c0.z + zv.w * c0.w;
        float d1 = zv.x * c1.x + zv.y * c1.y + zv.z * c1.z + zv.w * c1.w;
        float d2 = zv.x * c2.x + zv.y * c2.y + zv.z * c2.z + zv.w * c2.w;
        float d3 = zv.x * c3.x + zv.y * c3.y + zv.z * c3.z + zv.w * c3.w;
#pragma unroll
        for (int o = 16; o > 0; o >>= 1) {
            d0 += __shfl_xor_sync(0xffffffffu, d0, o);
            d1 += __shfl_xor_sync(0xffffffffu, d1, o);
            d2 += __shfl_xor_sync(0xffffffffu, d2, o);
            d3 += __shfl_xor_sync(0xffffffffu, d3, o);
        }
        float s0 = g_cnorm[cd.x] - 2.0f * d0;
        float s1 = g_cnorm[cd.y] - 2.0f * d1;
        float s2 = g_cnorm[cd.z] - 2.0f * d2;
        float s3 = g_cnorm[cd.w] - 2.0f * d3;

        float bs = s0; int bi = cd.x; float4 c = c0;
        if (s1 < bs || (s1 == bs && cd.y < bi)) { bs = s1; bi = cd.y; c = c1; }
        if (s2 < bs || (s2 == bs && cd.z < bi)) { bs = s2; bi = cd.z; c = c2; }
        if (s3 < bs || (s3 == bs && cd.w < bi)) { bs = s3; bi = cd.w; c = c3; }

        float dx = c.x - zv.x, dy = c.y - zv.y, dz = c.z - zv.z, dw = c.w - zv.w;
        float4 o4;
        o4.x = zv.x + dx; o4.y = zv.y + dy; o4.z = zv.z + dz; o4.w = zv.w + dw;
        ((float4*)(out + (size_t)t * DIM))[lane] = o4;

        float sq = dx * dx + dy * dy + dz * dz + dw * dw;
#pragma unroll
        for (int o = 16; o > 0; o >>= 1) sq += __shfl_xor_sync(0xffffffffu, sq, o);
        warp_sq += sq;
        if (lane == 0) atomicAdd(&g_counts[bi], 1);
    }
    if (lane == 0) swsq[warp] = warp_sq;
    __syncthreads();
    if (tid == 0) {
        double s = 0.0;
#pragma unroll
        for (int i = 0; i < 8; i++) s += (double)swsq[i];
        g_ssep[blockIdx.x] = s;
        __threadfence();
        unsigned int t = atomicAdd(&g_done, 1u);
        *sflag = (t == GRID_GEMM - 1) ? 1 : 0;
    }
    __syncthreads();

    /* ---- last CTA computes commit_loss + perplexity ---- */
    if (*sflag) {
        __threadfence();
        __shared__ double wd[8];
        __shared__ float wf[8];
        double sd = g_ssep[tid];
        float s = 0.0f;
        const float invT = 1.0f / (float)T_TOK;
        for (int i = tid; i < KC; i += 256) {
            float e = (float)g_counts[i] * invT;
            s += e * logf(e + 1e-8f);
        }
#pragma unroll
        for (int o = 16; o > 0; o >>= 1) {
            sd += __shfl_down_sync(0xffffffffu, sd, o);
            s  += __shfl_down_sync(0xffffffffu, s, o);
        }
        if (lane == 0) { wd[warp] = sd; wf[warp] = s; }
        __syncthreads();
        if (tid == 0) {
            double td = 0.0; float tf = 0.0f;
#pragma unroll
            for (int i = 0; i < 8; i++) { td += wd[i]; tf += wf[i]; }
            double mse = td / (double)((size_t)T_TOK * DIM);
            out[(size_t)T_TOK * DIM]     = (float)(1.25 * mse);
            out[(size_t)T_TOK * DIM + 1] = expf(-tf);
        }
    }
}

extern "C" void kernel_launch(void* const* d_in, const int* in_sizes, int n_in,
                              void* d_out, int out_size) {
    const float* z   = (const float*)d_in[0];
    const float* emb = (const float*)d_in[1];
    const float* pw  = (const float*)d_in[2];
    const float* pb  = (const float*)d_in[3];
    float* out = (float*)d_out;

    cudaFuncSetAttribute(k_proj, cudaFuncAttributeMaxDynamicSharedMemorySize, SMEM_PROJ);
    cudaFuncSetAttribute(k_gemm, cudaFuncAttributeMaxDynamicSharedMemorySize, SMEM_GEMM);

    k_proj<<<KC / 128, 256, SMEM_PROJ>>>(emb, pw, pb);
    k_gemm<<<GRID_GEMM, 256, SMEM_GEMM>>>(z, out);
}